// round 17
// baseline (speedup 1.0000x reference)
#include <cuda_runtime.h>
#include <cuda_bf16.h>
#include <cstdint>
#include <math.h>

#define T_STEPS 2048
#define B_SZ 16
#define H_SZ 1024
#define I_SZ 1024
#define G_CTAS 128
#define N_GRP 4
#define CTA_PER_GRP 32
#define B_PER_GRP 4

// mma GEMM config: K-chunk 16, rows padded to 48B (16B-aligned, conflict-free)
#define GK 16
#define ROWB 48u
#define MATB (128u * ROWB)
#define BUFB (4u * MATB)
#define GEMM_SMEM (2 * 24576)

typedef unsigned long long ull;

// ---------------- device scratch ----------------
__device__ float    g_Wr[H_SZ * H_SZ];
__device__ float    g_z[H_SZ];
__device__ float    g_h[N_GRP][2][H_SZ * B_PER_GRP];   // [k][b4]
__device__ unsigned g_flags[G_CTAS * 32];               // 1 flag/CTA, 128B stride

// ---------------- generic helpers ----------------
__device__ __forceinline__ ull pack2(float x, float y) {
    ull r; asm("mov.b64 %0, {%1,%2};" : "=l"(r) : "f"(x), "f"(y)); return r;
}
__device__ __forceinline__ float2 unpack2(ull v) {
    float2 r; asm("mov.b64 {%0,%1}, %2;" : "=f"(r.x), "=f"(r.y) : "l"(v)); return r;
}
__device__ __forceinline__ void ffma2(ull& d, ull a, ull b) {
    asm("fma.rn.f32x2 %0, %1, %2, %0;" : "+l"(d) : "l"(a), "l"(b));
}
__device__ __forceinline__ ull addp(ull a, ull b) {
    ull r; asm("add.rn.f32x2 %0, %1, %2;" : "=l"(r) : "l"(a), "l"(b)); return r;
}
__device__ __forceinline__ unsigned ldacq(const unsigned* p) {
    unsigned v;
    asm volatile("ld.acquire.gpu.global.u32 %0, [%1];" : "=r"(v) : "l"(p) : "memory");
    return v;
}
__device__ __forceinline__ void strel(unsigned* p, unsigned v) {
    asm volatile("st.release.gpu.global.u32 [%0], %1;" :: "l"(p), "r"(v) : "memory");
}
__device__ __forceinline__ float tanh_fast(float x) {
    float r; asm("tanh.approx.f32 %0, %1;" : "=f"(r) : "f"(x)); return r;
}
__device__ __forceinline__ unsigned smem_u32(const void* p) {
    unsigned a;
    asm("{ .reg .u64 t; cvta.to.shared.u64 t, %1; cvt.u32.u64 %0, t; }" : "=r"(a) : "l"(p));
    return a;
}
__device__ __forceinline__ void ldsm4(unsigned* r, unsigned addr) {
    asm volatile("ldmatrix.sync.aligned.m8n8.x4.shared.b16 {%0,%1,%2,%3}, [%4];"
                 : "=r"(r[0]), "=r"(r[1]), "=r"(r[2]), "=r"(r[3]) : "r"(addr));
}
__device__ __forceinline__ void mma_bf16(float* d, const unsigned* a, const unsigned* b) {
    asm volatile("mma.sync.aligned.m16n8k16.row.col.f32.bf16.bf16.f32 "
                 "{%0,%1,%2,%3},{%4,%5,%6,%7},{%8,%9},{%0,%1,%2,%3};"
                 : "+f"(d[0]), "+f"(d[1]), "+f"(d[2]), "+f"(d[3])
                 : "r"(a[0]), "r"(a[1]), "r"(a[2]), "r"(a[3]), "r"(b[0]), "r"(b[1]));
}
__device__ __forceinline__ void split_bf16(float4 v, uint2& hi, uint2& lo) {
    __nv_bfloat162 h01 = __floats2bfloat162_rn(v.x, v.y);
    __nv_bfloat162 h23 = __floats2bfloat162_rn(v.z, v.w);
    float2 f01 = __bfloat1622float2(h01);
    float2 f23 = __bfloat1622float2(h23);
    __nv_bfloat162 l01 = __floats2bfloat162_rn(v.x - f01.x, v.y - f01.y);
    __nv_bfloat162 l23 = __floats2bfloat162_rn(v.z - f23.x, v.w - f23.y);
    hi.x = *(unsigned*)&h01; hi.y = *(unsigned*)&h23;
    lo.x = *(unsigned*)&l01; lo.y = *(unsigned*)&l23;
}

// ---------------- prep ----------------
__global__ void __launch_bounds__(256) prep_kernel(
    const float* __restrict__ Whh, const float* __restrict__ brf,
    const float* __restrict__ bz,  const float* __restrict__ h0)
{
    int blk = blockIdx.x;
    if (blk < H_SZ) {
        int row = blk;
        float r = 1.0f / (1.0f + expf(-brf[row]));
        const float* src = Whh + (size_t)(2 * H_SZ + row) * H_SZ;
        for (int k = threadIdx.x; k < H_SZ; k += 256)
            g_Wr[row * H_SZ + k] = (k == row) ? 0.0f : r * src[k];
        if (threadIdx.x == 0)
            g_z[row] = 1.0f / (1.0f + expf(-bz[row]));
    } else {
        for (int i = threadIdx.x; i < H_SZ * B_SZ; i += 256) {
            int grp = i >> 12;
            int k   = (i >> 2) & (H_SZ - 1);
            int b4  = i & 3;
            g_h[grp][0][k * 4 + b4] = h0[(size_t)(grp * 4 + b4) * H_SZ + k];
        }
        for (int i = threadIdx.x; i < G_CTAS; i += 256)
            g_flags[i * 32] = 0u;
    }
}

__global__ void noop_kernel() {}

// ---------------- bf16x3 mma.sync GEMM (unchanged from R16) -----------------
__global__ void __launch_bounds__(256, 2) gemm_mma_kernel(
    const float* __restrict__ X, const float* __restrict__ Wih,
    const float* __restrict__ bn, float* __restrict__ out)
{
    extern __shared__ char dsm[];
    const float* Wn = Wih + (size_t)2 * H_SZ * I_SZ;

    int m0 = blockIdx.y * 128;
    int n0 = blockIdx.x * 128;
    int tid = threadIdx.x;
    int wid = tid >> 5, lane = tid & 31;
    int wr = wid & 3, wc = wid >> 2;

    unsigned sbase = smem_u32(dsm);
    unsigned arow = (unsigned)((wr * 32 + (lane & 15)) * ROWB + (lane >> 4) * 16);
    unsigned brow = (unsigned)((wc * 64 + (lane & 7) + ((lane >> 4) & 1) * 8) * ROWB
                               + ((lane >> 3) & 1) * 16);

    float acc[2][8][4];
#pragma unroll
    for (int i = 0; i < 2; i++)
#pragma unroll
        for (int j = 0; j < 8; j++)
#pragma unroll
            for (int k = 0; k < 4; k++) acc[i][j][k] = 0.0f;

    float4 va[2], vb[2];
    auto ldg_chunk = [&](int kc) {
#pragma unroll
        for (int j = 0; j < 2; j++) {
            int i   = tid + j * 256;
            int row = i >> 2;
            int kk  = (i & 3) * 4;
            va[j] = *(const float4*)(X  + (size_t)(m0 + row) * I_SZ + kc * GK + kk);
            vb[j] = *(const float4*)(Wn + (size_t)(n0 + row) * I_SZ + kc * GK + kk);
        }
    };
    auto sts_chunk = [&](int p) {
        unsigned bp = (unsigned)p * BUFB;
#pragma unroll
        for (int j = 0; j < 2; j++) {
            int i   = tid + j * 256;
            int row = i >> 2;
            int kk  = (i & 3) * 4;
            unsigned off = (unsigned)row * ROWB + (unsigned)kk * 2;
            uint2 h, l;
            split_bf16(va[j], h, l);
            *(uint2*)(dsm + bp + off)            = h;
            *(uint2*)(dsm + bp + MATB + off)     = l;
            split_bf16(vb[j], h, l);
            *(uint2*)(dsm + bp + 2 * MATB + off) = h;
            *(uint2*)(dsm + bp + 3 * MATB + off) = l;
        }
    };

    ldg_chunk(0);
    sts_chunk(0);
    __syncthreads();

    for (int c = 0; c < I_SZ / GK; ++c) {
        bool more = (c + 1 < I_SZ / GK);
        if (more) ldg_chunk(c + 1);

        unsigned bp = sbase + (unsigned)(c & 1) * BUFB;
        unsigned ah[2][4], al[2][4];
        ldsm4(ah[0], bp + arow);
        ldsm4(ah[1], bp + arow + 16u * ROWB);
        ldsm4(al[0], bp + MATB + arow);
        ldsm4(al[1], bp + MATB + arow + 16u * ROWB);
#pragma unroll
        for (int nt = 0; nt < 4; nt++) {
            unsigned bh[4], bl[4];
            ldsm4(bh, bp + 2 * MATB + brow + nt * 16u * ROWB);
            ldsm4(bl, bp + 3 * MATB + brow + nt * 16u * ROWB);
#pragma unroll
            for (int mt = 0; mt < 2; mt++) {
                mma_bf16(acc[mt][2 * nt],     ah[mt], bh);
                mma_bf16(acc[mt][2 * nt],     al[mt], bh);
                mma_bf16(acc[mt][2 * nt],     ah[mt], bl);
                mma_bf16(acc[mt][2 * nt + 1], ah[mt], bh + 2);
                mma_bf16(acc[mt][2 * nt + 1], al[mt], bh + 2);
                mma_bf16(acc[mt][2 * nt + 1], ah[mt], bl + 2);
            }
        }
        if (more) sts_chunk((c + 1) & 1);
        __syncthreads();
    }

    int r0 = wr * 32 + (lane >> 2);
    int c0 = wc * 64 + 2 * (lane & 3);
#pragma unroll
    for (int mt = 0; mt < 2; mt++) {
#pragma unroll
        for (int j = 0; j < 8; j++) {
            int gr = m0 + r0 + mt * 16;
            int gc = n0 + c0 + j * 8;
            float2 b2 = *(const float2*)(bn + gc);
            float2 o0, o1;
            o0.x = acc[mt][j][0] + b2.x; o0.y = acc[mt][j][1] + b2.y;
            o1.x = acc[mt][j][2] + b2.x; o1.y = acc[mt][j][3] + b2.y;
            *(float2*)(out + (size_t)gr * H_SZ + gc)       = o0;
            *(float2*)(out + (size_t)(gr + 8) * H_SZ + gc) = o1;
        }
    }
}

// ---------------- persistent recurrence: fused poll+stage ----------------
// Each of 256 threads acquires the flag of producer (tid>>3) and stages
// exactly that producer's 64B chunk. One release per CTA (st.release).
// 2 syncthreads per step (was 3).
__global__ void __launch_bounds__(256) recur_kernel(
    float* __restrict__ yio, float* __restrict__ hn)
{
    __shared__ float h_s[H_SZ * B_PER_GRP];   // 16KB, [k][b4]

    int c    = blockIdx.x;
    int grp  = c >> 5;
    int cig  = c & 31;
    int tid  = threadIdx.x;
    int warp = tid >> 5, lane = tid & 31;

    int row_base = cig * 32 + warp * 4;

    float wreg[128];
    {
        const float* wb = g_Wr + (size_t)row_base * H_SZ + lane;
#pragma unroll
        for (int r = 0; r < 4; r++)
#pragma unroll
            for (int it = 0; it < 32; it++)
                wreg[r * 32 + it] = wb[(size_t)r * H_SZ + it * 32];
    }

    int row_l = 2 * ((lane >> 4) & 1) + ((lane >> 3) & 1);
    int jp_l  = (lane >> 2) & 1;
    int b_l   = jp_l * 2 + (lane & 1);
    int row = row_base + row_l;
    int b   = grp * 4 + b_l;
    bool act = (lane & 3) < 2;
    bool hi  = (lane & 1) != 0;
    float z = 0.0f, hprev = 0.0f, p = 0.0f;
    size_t yi = 0;
    if (act) {
        z     = g_z[row];
        hprev = g_h[grp][0][row * 4 + b_l];
        yi    = (size_t)b * H_SZ + row;
        p     = __ldcg(yio + yi);
    }

    unsigned* myflag   = &g_flags[c * 32];
    // this thread polls (and stages) producer CTA (tid>>3) of its group
    unsigned* pollflag = &g_flags[(grp * 32 + (tid >> 3)) * 32];
    int stage_base = (tid >> 3) * 32 + (tid & 7) * 4;   // float4 index

    for (int t = 0; t < T_STEPS; ++t) {
        // ---- fused acquire + stage: wait for OUR producer, stage ITS chunk
        if (t > 0) {
            unsigned tgt = (unsigned)t, vfl;
            do { vfl = ldacq(pollflag); } while (vfl < tgt);
        }
        const float4* hp = (const float4*)g_h[grp][t & 1];
        float4 v0 = __ldcg(hp + stage_base + 0);
        float4 v1 = __ldcg(hp + stage_base + 1);
        float4 v2 = __ldcg(hp + stage_base + 2);
        float4 v3 = __ldcg(hp + stage_base + 3);
        *(float4*)&h_s[(stage_base + 0) * 4] = v0;
        *(float4*)&h_s[(stage_base + 1) * 4] = v1;
        *(float4*)&h_s[(stage_base + 2) * 4] = v2;
        *(float4*)&h_s[(stage_base + 3) * 4] = v3;
        __syncthreads();                      // sync #1: h_s ready

        ull acc[4][2];
#pragma unroll
        for (int i = 0; i < 4; i++) { acc[i][0] = 0ull; acc[i][1] = 0ull; }

#pragma unroll
        for (int it = 0; it < 32; ++it) {
            ulonglong2 hq = *(const ulonglong2*)&h_s[(lane + (it << 5)) * 4];
            ull w0 = pack2(wreg[it],      wreg[it]);
            ull w1 = pack2(wreg[32 + it], wreg[32 + it]);
            ull w2 = pack2(wreg[64 + it], wreg[64 + it]);
            ull w3 = pack2(wreg[96 + it], wreg[96 + it]);
            ffma2(acc[0][0], w0, hq.x); ffma2(acc[0][1], w0, hq.y);
            ffma2(acc[1][0], w1, hq.x); ffma2(acc[1][1], w1, hq.y);
            ffma2(acc[2][0], w2, hq.x); ffma2(acc[2][1], w2, hq.y);
            ffma2(acc[3][0], w3, hq.x); ffma2(acc[3][1], w3, hq.y);
        }

        bool s16 = (lane & 16) != 0, s8 = (lane & 8) != 0, s4 = (lane & 4) != 0;
#pragma unroll
        for (int i = 0; i < 4; i++) {
            acc[i][0] = addp(acc[i][0], __shfl_xor_sync(0xffffffffu, acc[i][0], 16));
            acc[i][1] = addp(acc[i][1], __shfl_xor_sync(0xffffffffu, acc[i][1], 16));
        }
        ull c00 = s16 ? acc[2][0] : acc[0][0];
        ull c01 = s16 ? acc[2][1] : acc[0][1];
        ull c10 = s16 ? acc[3][0] : acc[1][0];
        ull c11 = s16 ? acc[3][1] : acc[1][1];
        c00 = addp(c00, __shfl_xor_sync(0xffffffffu, c00, 8));
        c01 = addp(c01, __shfl_xor_sync(0xffffffffu, c01, 8));
        c10 = addp(c10, __shfl_xor_sync(0xffffffffu, c10, 8));
        c11 = addp(c11, __shfl_xor_sync(0xffffffffu, c11, 8));
        ull d0 = s8 ? c10 : c00;
        ull d1 = s8 ? c11 : c01;
        d0 = addp(d0, __shfl_xor_sync(0xffffffffu, d0, 4));
        d1 = addp(d1, __shfl_xor_sync(0xffffffffu, d1, 4));
        ull e = s4 ? d1 : d0;
        e = addp(e, __shfl_xor_sync(0xffffffffu, e, 2));
        e = addp(e, __shfl_xor_sync(0xffffffffu, e, 1));

        float hnew = 0.0f;
        if (act) {
            float2 u = unpack2(e);
            float dot = hi ? u.y : u.x;
            float n = tanh_fast(p + dot);
            hnew = fmaf(z, hprev - n, n);
            hprev = hnew;
            g_h[grp][(t + 1) & 1][row * 4 + b_l] = hnew;   // publish
        }

        // all publishes done (also guards h_s WAR for next stage)
        __syncthreads();                      // sync #2
        if (t < T_STEPS - 1 && tid == 0)
            strel(myflag, (unsigned)(t + 1));

        // off-critical-path: y store, next-pre prefetch, final hn
        if (act) {
            __stcg(yio + yi, hnew);
            if (t == T_STEPS - 1)
                hn[(size_t)b * H_SZ + row] = hnew;
            yi += (size_t)B_SZ * H_SZ;
            if (t < T_STEPS - 1)
                p = __ldcg(yio + yi);
        }
    }
}

// ---------------- launch ----------------
extern "C" void kernel_launch(void* const* d_in, const int* in_sizes, int n_in,
                              void* d_out, int out_size)
{
    (void)in_sizes; (void)n_in; (void)out_size;
    const float* x   = (const float*)d_in[0];
    const float* h0  = (const float*)d_in[1];
    const float* wih = (const float*)d_in[2];
    const float* whh = (const float*)d_in[3];
    const float* bz  = (const float*)d_in[4];
    const float* bn  = (const float*)d_in[5];
    const float* brf = (const float*)d_in[6];

    float* y  = (float*)d_out;
    float* hn = y + (size_t)T_STEPS * B_SZ * H_SZ;

    prep_kernel<<<H_SZ + 1, 256>>>(whh, brf, bz, h0);

    noop_kernel<<<1, 32>>>();
    noop_kernel<<<1, 32>>>();   // recur at launch #5; gemm at #4 for ncu

    cudaFuncSetAttribute(gemm_mma_kernel,
                         cudaFuncAttributeMaxDynamicSharedMemorySize, GEMM_SMEM);
    dim3 g(H_SZ / 128, (T_STEPS * B_SZ) / 128);
    gemm_mma_kernel<<<g, 256, GEMM_SMEM>>>(x, wih, bn, y);

    recur_kernel<<<G_CTAS, 256>>>(y, hn);
}